// round 4
// baseline (speedup 1.0000x reference)
#include <cuda_runtime.h>
#include <cstdint>

// DiagonalSISOCell: V=100000, D=64, N=16
// out[v,d,q] = sum_n ( exp(delta_v*A[d,n])*state[v,d,n] + delta_v*B[d,n]*x[v,d] ) * C[d,n,q]
// delta_v = softplus(x[v,:] @ w_delta + b_delta)

#define V_TOK 100000
#define VPAD  100224          // multiple of 64; keeps bulk-copy rows 16B-aligned
#define LOG2E 1.4426950408889634f

__device__ float g_delta[VPAD];
__device__ float g_dxT[64 * VPAD];   // dxT[d][v] = delta_v * x[v,d]

// ---- smem layout (floats) ---------------------------------------------------
#define PITCH     68                  // 272B rows: conflict-free LDS.128
#define TILE_F    (64 * PITCH)        // 4352
#define OFF_C     0                   // C_s[4][16][16]         (1024)
#define OFF_AB    1024                // AB_s[4][16] float2     (128)
#define OFF_IN    1152                // in[3][TILE_F]          (13056)
#define OFF_OUT   14208               // out[2][TILE_F]         (8704)
#define OFF_DX    22912               // dx[3][4][64]           (768)
#define OFF_DELTA 23680               // delta[3][64]           (192)
#define SMEM_FLOATS 23872             // 95488 B

// ---------------------------------------------------------------------------
__device__ __forceinline__ float2 ffma2(float2 a, float2 b, float2 c) {
    float2 r;
    asm("fma.rn.f32x2 %0, %1, %2, %3;"
        : "=l"(*reinterpret_cast<unsigned long long*>(&r))
        : "l"(*reinterpret_cast<unsigned long long*>(&a)),
          "l"(*reinterpret_cast<unsigned long long*>(&b)),
          "l"(*reinterpret_cast<unsigned long long*>(&c)));
    return r;
}
__device__ __forceinline__ float ex2_approx(float x) {
    float r; asm("ex2.approx.f32 %0, %1;" : "=f"(r) : "f"(x)); return r;
}
__device__ __forceinline__ uint32_t smem_u32(const void* p) {
    uint32_t a;
    asm("{ .reg .u64 t; cvta.to.shared.u64 t, %1; cvt.u32.u64 %0, t; }"
        : "=r"(a) : "l"(p));
    return a;
}
__device__ __forceinline__ void bulk_g2s(uint32_t dst, const void* src,
                                         uint32_t bytes, uint32_t mbar) {
    asm volatile(
        "cp.async.bulk.shared::cluster.global.mbarrier::complete_tx::bytes "
        "[%0], [%1], %2, [%3];"
        :: "r"(dst), "l"(src), "r"(bytes), "r"(mbar) : "memory");
}
__device__ __forceinline__ void bulk_s2g(void* dst, uint32_t src, uint32_t bytes) {
    asm volatile("cp.async.bulk.global.shared::cta.bulk_group [%0], [%1], %2;"
                 :: "l"(dst), "r"(src), "r"(bytes) : "memory");
}
__device__ __forceinline__ void mbar_init(uint32_t mbar, uint32_t cnt) {
    asm volatile("mbarrier.init.shared.b64 [%0], %1;" :: "r"(mbar), "r"(cnt) : "memory");
}
__device__ __forceinline__ void mbar_arrive_tx(uint32_t mbar, uint32_t bytes) {
    asm volatile("mbarrier.arrive.expect_tx.shared.b64 _, [%0], %1;"
                 :: "r"(mbar), "r"(bytes) : "memory");
}
__device__ __forceinline__ void mbar_arrive(uint32_t mbar) {
    asm volatile("mbarrier.arrive.shared.b64 _, [%0];" :: "r"(mbar) : "memory");
}
__device__ __forceinline__ void mbar_wait(uint32_t mbar, uint32_t parity) {
    asm volatile(
        "{\n\t.reg .pred P;\n\t"
        "W_%=:\n\t"
        "mbarrier.try_wait.parity.acquire.cta.shared::cta.b64 P, [%0], %1, 0x989680;\n\t"
        "@!P bra W_%=;\n\t}"
        :: "r"(mbar), "r"(parity) : "memory");
}
__device__ __forceinline__ void bulk_commit() {
    asm volatile("cp.async.bulk.commit_group;" ::: "memory");
}
__device__ __forceinline__ void bulk_wait_read1() {
    asm volatile("cp.async.bulk.wait_group.read 1;" ::: "memory");
}
__device__ __forceinline__ void bulk_wait0() {
    asm volatile("cp.async.bulk.wait_group 0;" ::: "memory");
}
__device__ __forceinline__ void fence_async() {
    asm volatile("fence.proxy.async.shared::cta;" ::: "memory");
}

// ---------------------------------------------------------------------------
// Kernel 1: per 32-token block — delta[v] (softplus) and transposed
// dxT[d][v] = delta_v * x[v,d] with coalesced reads AND writes.
// ---------------------------------------------------------------------------
__global__ void __launch_bounds__(128)
delta_kernel(const float* __restrict__ x,
             const float* __restrict__ w,
             const float* __restrict__ b)
{
    __shared__ float xs[32 * 65];   // pitch 65: conflict-free column reads
    __shared__ float ws[64];
    __shared__ float ds[32];

    const int tid = threadIdx.x;
    const int v0  = blockIdx.x * 32;

    if (tid < 64) ws[tid] = w[tid];

    // coalesced load of x[v0..v0+31, 0..63]
#pragma unroll
    for (int j = 0; j < 16; j++) {
        int idx = j * 128 + tid;           // 0..2047
        int row = idx >> 6, col = idx & 63;
        xs[row * 65 + col] = x[(size_t)v0 * 64 + idx];
    }
    __syncthreads();

    // delta: 4 threads per token
    {
        int t = tid >> 2, sub = tid & 3;
        float s = 0.f;
        const float* xr = xs + t * 65 + sub * 16;
        const float* wr = ws + sub * 16;
#pragma unroll
        for (int k = 0; k < 16; k++) s = fmaf(xr[k], wr[k], s);
        s += __shfl_xor_sync(0xffffffffu, s, 1);
        s += __shfl_xor_sync(0xffffffffu, s, 2);
        if (sub == 0) {
            float tt = s + b[0];
            ds[t] = fmaxf(tt, 0.0f) + log1pf(expf(-fabsf(tt)));
        }
    }
    __syncthreads();

    if (tid < 32) g_delta[v0 + tid] = ds[tid];

    // dxT writes: warp-coalesced 128B rows
#pragma unroll
    for (int j = 0; j < 16; j++) {
        int d = j * 4 + (tid >> 5);
        int t = tid & 31;
        g_dxT[(size_t)d * VPAD + v0 + t] = ds[t] * xs[t * 65 + d];
    }
}

// ---------------------------------------------------------------------------
// Kernel 2: bulk-DMA main kernel, 3-deep input pipeline, 2 output buffers.
// Block = 128 thr = 4 warps; warp w owns d = grp*4 + w; tile = 64 tokens.
// ---------------------------------------------------------------------------
__global__ void __launch_bounds__(128, 2)
siso_kernel(const float* __restrict__ state,
            const float* __restrict__ log_nA,
            const float* __restrict__ Bm,
            const float* __restrict__ Cm,
            float* __restrict__ out,
            int chunk_sz)
{
    extern __shared__ float sm[];
    __shared__ __align__(8) unsigned long long mbar_store[3];

    const int tid   = threadIdx.x;
    const int w     = tid >> 5;
    const int l     = tid & 31;
    const int grp   = blockIdx.x & 15;     // 16 d-groups of 4
    const int chunk = blockIdx.x >> 4;

    const uint32_t smb = smem_u32(sm);
    uint32_t mb[3];
#pragma unroll
    for (int k = 0; k < 3; k++) mb[k] = smem_u32(&mbar_store[k]);

    if (tid == 0) {
        mbar_init(mb[0], 69); mbar_init(mb[1], 69); mbar_init(mb[2], 69);
    }

    // stage C slice + (A*log2e, B) pairs
    {
        const float* src = Cm + grp * 4 * 256;
        for (int i = tid; i < 1024; i += 128) sm[OFF_C + i] = src[i];
        if (tid < 64) {
            int dl = tid >> 4, n = tid & 15;
            int gd = grp * 4 + dl;
            float A2 = -__expf(log_nA[gd * 16 + n]) * LOG2E;
            reinterpret_cast<float2*>(sm + OFF_AB)[tid] =
                make_float2(A2, Bm[gd * 16 + n]);
        }
    }
    __syncthreads();   // mbar init + C/AB visible

    const int v_base  = chunk * chunk_sz;
    const int v_end   = min(V_TOK, v_base + chunk_sz);
    const int n_tiles = (v_end - v_base + 63) >> 6;

    const float* state_row = state + (size_t)v_base * 1024 + grp * 64 + (size_t)tid * 1024;
    const float* dx_row    = g_dxT + (size_t)(grp * 4 + (tid - 64)) * VPAD + v_base;

    // --- issue input DMA for tile ti into buffer b --------------------------
    auto issue = [&](int ti, int b) {
        const int nt = min(64, v_end - v_base - ti * 64);
        const uint32_t m = mb[b];
        if (tid < 64) {
            if (tid < nt) {
                mbar_arrive_tx(m, 256);
                bulk_g2s(smb + (OFF_IN + b * TILE_F + tid * PITCH) * 4,
                         state_row + (size_t)ti * 65536, 256, m);
            } else {
                mbar_arrive(m);
            }
        } else if (tid < 68) {
            uint32_t bytes = (uint32_t)(nt * 4);
            mbar_arrive_tx(m, bytes);
            bulk_g2s(smb + (OFF_DX + b * 256 + (tid - 64) * 64) * 4,
                     dx_row + ti * 64, bytes, m);
        } else if (tid == 68) {
            uint32_t bytes = (uint32_t)(nt * 4);
            mbar_arrive_tx(m, bytes);
            bulk_g2s(smb + (OFF_DELTA + b * 64) * 4,
                     g_delta + v_base + ti * 64, bytes, m);
        }
    };

    // prologue: fill up to 3 buffers
    issue(0, 0);
    if (n_tiles > 1) issue(1, 1);
    if (n_tiles > 2) issue(2, 2);

    const float*  Cw  = sm + OFF_C + w * 256;
    const float2* ABw = reinterpret_cast<const float2*>(sm + OFF_AB) + w * 16;

    int b = 0, ph = 0;
    for (int i = 0; i < n_tiles; i++) {
        const int o  = i & 1;
        const int v0 = v_base + i * 64;
        const int nt = min(64, v_end - v0);

        mbar_wait(mb[b], ph);

        // ---- compute: lane owns tokens l and l+32 ---------------------------
        const float* in_t = sm + OFF_IN + b * TILE_F;
        const float delta_a = sm[OFF_DELTA + b * 64 + l];
        const float delta_c = sm[OFF_DELTA + b * 64 + l + 32];
        const float dx_a = sm[OFF_DX + b * 256 + w * 64 + l];
        const float dx_c = sm[OFF_DX + b * 256 + w * 64 + l + 32];

        const float* ra = in_t + l * PITCH + w * 16;
        const float* rb = in_t + (l + 32) * PITCH + w * 16;

        float2 acc_a[8], acc_c[8];
#pragma unroll
        for (int p = 0; p < 8; p++) {
            acc_a[p] = make_float2(0.f, 0.f);
            acc_c[p] = make_float2(0.f, 0.f);
        }

        float4 s4a, s4b;
#pragma unroll
        for (int n = 0; n < 16; n++) {
            if ((n & 3) == 0) {
                s4a = *reinterpret_cast<const float4*>(ra + n);
                s4b = *reinterpret_cast<const float4*>(rb + n);
            }
            float s_a = (n & 3) == 0 ? s4a.x : (n & 3) == 1 ? s4a.y : (n & 3) == 2 ? s4a.z : s4a.w;
            float s_c = (n & 3) == 0 ? s4b.x : (n & 3) == 1 ? s4b.y : (n & 3) == 2 ? s4b.z : s4b.w;

            float2 ab = ABw[n];
            float e_a = ex2_approx(delta_a * ab.x);
            float e_c = ex2_approx(delta_c * ab.x);
            float nv_a = fmaf(e_a, s_a, dx_a * ab.y);
            float nv_c = fmaf(e_c, s_c, dx_c * ab.y);
            float2 va = make_float2(nv_a, nv_a);
            float2 vc = make_float2(nv_c, nv_c);

            const float4* crow = reinterpret_cast<const float4*>(Cw + n * 16);
#pragma unroll
            for (int p4 = 0; p4 < 4; p4++) {
                float4 c4 = crow[p4];                    // broadcast LDS.128
                float2 c01 = make_float2(c4.x, c4.y);
                float2 c23 = make_float2(c4.z, c4.w);
                acc_a[2 * p4]     = ffma2(va, c01, acc_a[2 * p4]);
                acc_a[2 * p4 + 1] = ffma2(va, c23, acc_a[2 * p4 + 1]);
                acc_c[2 * p4]     = ffma2(vc, c01, acc_c[2 * p4]);
                acc_c[2 * p4 + 1] = ffma2(vc, c23, acc_c[2 * p4 + 1]);
            }
        }

        // ---- allow out[o] reuse: tile i-2's store must have consumed smem ---
        if (tid < 64) bulk_wait_read1();
        __syncthreads();            // all warps: compute(i) done, drain visible

        // refill this input buffer for tile i+3 (safe: everyone past compute)
        if (i + 3 < n_tiles) issue(i + 3, b);

        // ---- assemble output rows in smem ------------------------------------
        float* oa = sm + OFF_OUT + o * TILE_F + l * PITCH + w * 16;
        float* oc = sm + OFF_OUT + o * TILE_F + (l + 32) * PITCH + w * 16;
#pragma unroll
        for (int p4 = 0; p4 < 4; p4++) {
            *reinterpret_cast<float4*>(oa + 4 * p4) =
                make_float4(acc_a[2 * p4].x, acc_a[2 * p4].y,
                            acc_a[2 * p4 + 1].x, acc_a[2 * p4 + 1].y);
            *reinterpret_cast<float4*>(oc + 4 * p4) =
                make_float4(acc_c[2 * p4].x, acc_c[2 * p4].y,
                            acc_c[2 * p4 + 1].x, acc_c[2 * p4 + 1].y);
        }
        __syncthreads();

        // ---- bulk store: one 256B row per thread -----------------------------
        if (tid < 64) {
            fence_async();
            if (tid < nt)
                bulk_s2g(out + (size_t)(v0 + tid) * 1024 + grp * 64,
                         smb + (OFF_OUT + o * TILE_F + tid * PITCH) * 4, 256);
            bulk_commit();
        }

        // advance buffer cursor
        if (++b == 3) { b = 0; ph ^= 1; }
    }

    if (tid < 64) bulk_wait0();
}

// ---------------------------------------------------------------------------
// Launch
// ---------------------------------------------------------------------------
extern "C" void kernel_launch(void* const* d_in, const int* in_sizes, int n_in,
                              void* d_out, int out_size)
{
    const float* x       = (const float*)d_in[0];  // [V, D]
    const float* state   = (const float*)d_in[1];  // [V, D, N]
    const float* log_nA  = (const float*)d_in[2];  // [D, N]
    const float* B       = (const float*)d_in[3];  // [D, N]
    const float* C       = (const float*)d_in[4];  // [D, N, N]
    const float* w_delta = (const float*)d_in[5];  // [1, D]
    const float* b_delta = (const float*)d_in[6];  // [1]
    float* out = (float*)d_out;                    // [V, D, N]

    // Kernel 1: delta + transposed dx (32 tokens per block)
    delta_kernel<<<V_TOK / 32, 128>>>(x, w_delta, b_delta);

    // Kernel 2: 16 d-groups x 18 chunks = 288 blocks (2/SM, single wave)
    const int n_chunks = 18;
    const int chunk_sz = 5568;                     // 87 tiles of 64; 18*5568 >= V
    const int smem_bytes = SMEM_FLOATS * 4;        // 95488 B

    cudaFuncSetAttribute(siso_kernel,
                         cudaFuncAttributeMaxDynamicSharedMemorySize, smem_bytes);
    siso_kernel<<<16 * n_chunks, 128, smem_bytes>>>(state, log_nA, B, C, out, chunk_sz);
}

// round 5
// speedup vs baseline: 1.2298x; 1.2298x over previous
#include <cuda_runtime.h>
#include <cstdint>

// DiagonalSISOCell: V=100000, D=64, N=16
// out[v,d,q] = sum_n ( exp(delta_v*A[d,n])*state[v,d,n] + delta_v*B[d,n]*x[v,d] ) * C[d,n,q]
// delta_v = softplus(x[v,:] @ w_delta + b_delta)

#define V_TOK 100000
#define VPAD  100224
#define LOG2E 1.4426950408889634f

__device__ float g_delta[VPAD];
__device__ float g_dxT[64 * VPAD];   // dxT[d][v] = delta_v * x[v,d]

// ---------------------------------------------------------------------------
__device__ __forceinline__ float2 ffma2(float2 a, float2 b, float2 c) {
    float2 r;
    asm("fma.rn.f32x2 %0, %1, %2, %3;"
        : "=l"(*reinterpret_cast<unsigned long long*>(&r))
        : "l"(*reinterpret_cast<unsigned long long*>(&a)),
          "l"(*reinterpret_cast<unsigned long long*>(&b)),
          "l"(*reinterpret_cast<unsigned long long*>(&c)));
    return r;
}
__device__ __forceinline__ float ex2_approx(float x) {
    float r; asm("ex2.approx.f32 %0, %1;" : "=f"(r) : "f"(x)); return r;
}

// ---------------------------------------------------------------------------
// Kernel 1: per 32-token block — delta[v] (softplus) and transposed
// dxT[d][v] = delta_v * x[v,d], coalesced reads AND writes.
// ---------------------------------------------------------------------------
__global__ void __launch_bounds__(128)
delta_kernel(const float* __restrict__ x,
             const float* __restrict__ w,
             const float* __restrict__ b)
{
    __shared__ float xs[32 * 65];
    __shared__ float ws[64];
    __shared__ float ds[32];

    const int tid = threadIdx.x;
    const int v0  = blockIdx.x * 32;

    if (tid < 64) ws[tid] = w[tid];

#pragma unroll
    for (int j = 0; j < 16; j++) {
        int idx = j * 128 + tid;
        int row = idx >> 6, col = idx & 63;
        xs[row * 65 + col] = x[(size_t)v0 * 64 + idx];
    }
    __syncthreads();

    {
        int t = tid >> 2, sub = tid & 3;
        float s = 0.f;
        const float* xr = xs + t * 65 + sub * 16;
        const float* wr = ws + sub * 16;
#pragma unroll
        for (int k = 0; k < 16; k++) s = fmaf(xr[k], wr[k], s);
        s += __shfl_xor_sync(0xffffffffu, s, 1);
        s += __shfl_xor_sync(0xffffffffu, s, 2);
        if (sub == 0) {
            float tt = s + b[0];
            ds[t] = fmaxf(tt, 0.0f) + log1pf(expf(-fabsf(tt)));
        }
    }
    __syncthreads();

    if (tid < 32) g_delta[v0 + tid] = ds[tid];

#pragma unroll
    for (int j = 0; j < 16; j++) {
        int d = j * 4 + (tid >> 5);
        int t = tid & 31;
        g_dxT[(size_t)d * VPAD + v0 + t] = ds[t] * xs[t * 65 + d];
    }
}

// ---------------------------------------------------------------------------
// Kernel 2: R2-style per-warp streaming kernel (no block syncs in hot loop).
// Block = 256 thr = 8 warps; warp w owns feature d = grp*8 + w; 64-token
// tiles through a pitch-20 smem transpose buffer (in and out reuse it).
// delta / dx come from contiguous precomputed arrays (1 wavefront per load).
// ---------------------------------------------------------------------------
__global__ void __launch_bounds__(256, 3)
siso_kernel(const float* __restrict__ state,
            const float* __restrict__ log_nA,
            const float* __restrict__ Bm,
            const float* __restrict__ Cm,
            float* __restrict__ out,
            int chunk_sz)
{
    extern __shared__ float sm[];
    // C_s[8][256] @0 | AB_s[8][16] float2 @2048 | tiles[8][64*20] @2304
    float*  C_s      = sm;
    float2* AB_s     = reinterpret_cast<float2*>(sm + 2048);
    float*  tile_all = sm + 2304;

    const int tid   = threadIdx.x;
    const int w     = tid >> 5;
    const int l     = tid & 31;
    const int grp   = blockIdx.x & 7;
    const int chunk = blockIdx.x >> 3;
    const int d     = grp * 8 + w;

    {
        const float* src = Cm + grp * 8 * 256;
        for (int i = tid; i < 2048; i += 256) C_s[i] = src[i];
        if (tid < 128) {
            int dl = tid >> 4, n = tid & 15;
            int gd = grp * 8 + dl;
            float A2 = -__expf(log_nA[gd * 16 + n]) * LOG2E;
            AB_s[tid] = make_float2(A2, Bm[gd * 16 + n]);
        }
    }
    __syncthreads();

    float*        tile = tile_all + w * (64 * 20);
    const float2* ABw  = AB_s + w * 16;
    const float*  Cw   = C_s + w * 256;

    const int v_start = chunk * chunk_sz;
    const int v_end   = min(V_TOK, v_start + chunk_sz);

    const int lt = l >> 2;    // loader token sub-index (0..7)
    const int lg = l & 3;     // loader 16B group (0..3)

    const float4* sp_base  = reinterpret_cast<const float4*>(state) + d * 4 + lg;
    const float*  dx_base  = g_dxT + (size_t)d * VPAD;

    for (int v0 = v_start; v0 < v_end; v0 += 64) {
        const int nt = min(64, v_end - v0);
        const float4* sp = sp_base + (size_t)v0 * 256;

        __syncwarp();   // prior iteration's tile readers (this warp) are done
        // 1. coalesced state load -> smem transpose, 2 batches of 4 float4
#pragma unroll
        for (int io = 0; io < 2; io++) {
            float4 r[4];
#pragma unroll
            for (int i = 0; i < 4; i++) {
                int t = lt + 8 * (io * 4 + i);
                r[i] = (t < nt) ? sp[(size_t)t * 256] : make_float4(0.f, 0.f, 0.f, 0.f);
            }
#pragma unroll
            for (int i = 0; i < 4; i++) {
                int t = lt + 8 * (io * 4 + i);
                *reinterpret_cast<float4*>(tile + t * 20 + lg * 4) = r[i];
            }
        }
        __syncwarp();

        // 2. per-lane token scalars (contiguous loads: 1 wavefront each)
        const bool va = (l < nt);
        const bool vc = (l + 32 < nt);
        const float delta_a = va ? __ldg(&g_delta[v0 + l])       : 0.f;
        const float delta_c = vc ? __ldg(&g_delta[v0 + 32 + l])  : 0.f;
        const float dx_a    = va ? __ldg(&dx_base[v0 + l])       : 0.f;
        const float dx_c    = vc ? __ldg(&dx_base[v0 + 32 + l])  : 0.f;

        const float* ra = tile + l * 20;
        const float* rb = tile + (l + 32) * 20;

        float2 acc_a[8], acc_c[8];
#pragma unroll
        for (int p = 0; p < 8; p++) {
            acc_a[p] = make_float2(0.f, 0.f);
            acc_c[p] = make_float2(0.f, 0.f);
        }

        // 3. recurrence + contraction, one exp per element
        float4 s4a, s4b;
#pragma unroll
        for (int n = 0; n < 16; n++) {
            if ((n & 3) == 0) {
                s4a = *reinterpret_cast<const float4*>(ra + n);
                s4b = *reinterpret_cast<const float4*>(rb + n);
            }
            float s_a = (n & 3) == 0 ? s4a.x : (n & 3) == 1 ? s4a.y : (n & 3) == 2 ? s4a.z : s4a.w;
            float s_c = (n & 3) == 0 ? s4b.x : (n & 3) == 1 ? s4b.y : (n & 3) == 2 ? s4b.z : s4b.w;

            float2 ab = ABw[n];
            float e_a = ex2_approx(delta_a * ab.x);
            float e_c = ex2_approx(delta_c * ab.x);
            float nv_a = fmaf(e_a, s_a, dx_a * ab.y);
            float nv_c = fmaf(e_c, s_c, dx_c * ab.y);
            float2 vva = make_float2(nv_a, nv_a);
            float2 vvc = make_float2(nv_c, nv_c);

            const float4* crow = reinterpret_cast<const float4*>(Cw + n * 16);
#pragma unroll
            for (int p4 = 0; p4 < 4; p4++) {
                float4 c4 = crow[p4];                      // broadcast LDS.128
                float2 c01 = make_float2(c4.x, c4.y);
                float2 c23 = make_float2(c4.z, c4.w);
                acc_a[2 * p4]     = ffma2(vva, c01, acc_a[2 * p4]);
                acc_a[2 * p4 + 1] = ffma2(vva, c23, acc_a[2 * p4 + 1]);
                acc_c[2 * p4]     = ffma2(vvc, c01, acc_c[2 * p4]);
                acc_c[2 * p4 + 1] = ffma2(vvc, c23, acc_c[2 * p4 + 1]);
            }
        }

        // 4. transpose out through the same tile, then coalesced store
        __syncwarp();
        float* oa = tile + l * 20;
        float* oc = tile + (l + 32) * 20;
#pragma unroll
        for (int p4 = 0; p4 < 4; p4++) {
            *reinterpret_cast<float4*>(oa + 4 * p4) =
                make_float4(acc_a[2 * p4].x, acc_a[2 * p4].y,
                            acc_a[2 * p4 + 1].x, acc_a[2 * p4 + 1].y);
            *reinterpret_cast<float4*>(oc + 4 * p4) =
                make_float4(acc_c[2 * p4].x, acc_c[2 * p4].y,
                            acc_c[2 * p4 + 1].x, acc_c[2 * p4 + 1].y);
        }
        __syncwarp();

        float4* op = reinterpret_cast<float4*>(out) + (size_t)v0 * 256 + d * 4 + lg;
#pragma unroll
        for (int io = 0; io < 2; io++) {
#pragma unroll
            for (int i = 0; i < 4; i++) {
                int t = lt + 8 * (io * 4 + i);
                float4 vo = *reinterpret_cast<const float4*>(tile + t * 20 + lg * 4);
                if (t < nt) op[(size_t)t * 256] = vo;
            }
        }
    }
}

// ---------------------------------------------------------------------------
// Launch
// ---------------------------------------------------------------------------
extern "C" void kernel_launch(void* const* d_in, const int* in_sizes, int n_in,
                              void* d_out, int out_size)
{
    const float* x       = (const float*)d_in[0];  // [V, D]
    const float* state   = (const float*)d_in[1];  // [V, D, N]
    const float* log_nA  = (const float*)d_in[2];  // [D, N]
    const float* B       = (const float*)d_in[3];  // [D, N]
    const float* C       = (const float*)d_in[4];  // [D, N, N]
    const float* w_delta = (const float*)d_in[5];  // [1, D]
    const float* b_delta = (const float*)d_in[6];  // [1]
    float* out = (float*)d_out;                    // [V, D, N]

    // Kernel 1: delta + transposed dx
    delta_kernel<<<V_TOK / 32, 128>>>(x, w_delta, b_delta);

    // Kernel 2: 8 d-groups x 55 chunks = 440 blocks (3/SM target, 1 wave)
    const int n_chunks = 55;
    const int chunk_sz = 1856;                     // 29 tiles of 64; 55*1856 >= V
    const int smem_bytes = (2048 + 256 + 8 * 64 * 20) * 4;   // 50176 B

    cudaFuncSetAttribute(siso_kernel,
                         cudaFuncAttributeMaxDynamicSharedMemorySize, smem_bytes);
    siso_kernel<<<8 * n_chunks, 256, smem_bytes>>>(state, log_nA, B, C, out, chunk_sz);
}